// round 6
// baseline (speedup 1.0000x reference)
#include <cuda_runtime.h>
#include <math.h>

#define F32_INF __int_as_float(0x7f800000)

// ---------------- problem constants ----------------
#define NB 8
#define NS 512
#define NE 768
#define NGE 32
#define NHD 384
#define NL 4096
#define LAMBDA_INIT 0.2f
#define SCALING 0.05103103630798287f   // 384^-0.5

// ---------------- scratch (__device__ globals; no allocation allowed) ----------------
__device__ float g_Q[NB * NS * NE];                      // 12.6 MB
__device__ float g_KV[(size_t)NB * NL * 2 * NE];         // 201 MB  (K | V interleaved, ld=1536)
__device__ float g_S[(size_t)NB * 2 * NS * NL];          // 134 MB  raw scores, per (b,h)
__device__ float g_AO[NB * NS * NE];                     // attn_out pre-norm
__device__ float g_X[NB * NS * NE];                      // normed
__device__ float g_lambda;
__device__ int   g_mask_mode;                            // 0=uint8, 1=int32, 2=float32

// ---------------- mask dtype detection (device-side; bool isn't a harness dtype) ----------------
__global__ void detect_mask_kernel(const unsigned char* __restrict__ km) {
    __shared__ int s_non01, s_nonmult4;
    if (threadIdx.x == 0) { s_non01 = 0; s_nonmult4 = 0; }
    __syncthreads();
    int non01 = 0, nm4 = 0;
    for (int i = threadIdx.x; i < 32768; i += 256) {
        unsigned char v = km[i];
        if (v > 1) non01 = 1;
        if (v != 0 && (i & 3) != 0) nm4 = 1;
    }
    if (non01) atomicOr(&s_non01, 1);
    if (nm4)   atomicOr(&s_nonmult4, 1);
    __syncthreads();
    if (threadIdx.x == 0)
        g_mask_mode = s_non01 ? 2 : (s_nonmult4 ? 0 : 1);
}

__device__ __forceinline__ bool mask_at(const void* p, long idx, int mode) {
    if (mode == 1) return ((const int*)p)[idx] != 0;
    if (mode == 2) return ((const float*)p)[idx] != 0.0f;
    return ((const unsigned char*)p)[idx] != 0;
}

// ---------------- lambda scalar ----------------
__global__ void lambda_kernel(const float* __restrict__ lq1, const float* __restrict__ lk1,
                              const float* __restrict__ lq2, const float* __restrict__ lk2) {
    __shared__ float red1[12], red2[12];
    int t = threadIdx.x;  // 384 threads = 12 warps
    float a = lq1[t] * lk1[t];
    float b = lq2[t] * lk2[t];
    #pragma unroll
    for (int o = 16; o > 0; o >>= 1) {
        a += __shfl_xor_sync(0xFFFFFFFFu, a, o);
        b += __shfl_xor_sync(0xFFFFFFFFu, b, o);
    }
    if ((t & 31) == 0) { red1[t >> 5] = a; red2[t >> 5] = b; }
    __syncthreads();
    if (t == 0) {
        float s1 = 0.f, s2 = 0.f;
        for (int i = 0; i < 12; i++) { s1 += red1[i]; s2 += red2[i]; }
        g_lambda = expf(s1) - expf(s2) + LAMBDA_INIT;
    }
}

// ---------------- generic tiled fp32 GEMM ----------------
// C[M,N] = alpha * A[M,K] @ (TB ? B[N,K]^T : B[K,N])
// batch offset: (z/div)*sHi + (z%div)*sLo for each of A,B,C.
// Requires M%64==0, N%64==0, K%16==0 (true for all call sites here).
template <bool TB>
__global__ __launch_bounds__(256) void gemm_kernel(
    const float* __restrict__ A, const float* __restrict__ B, float* __restrict__ C,
    int M, int N, int K, int lda, int ldb, int ldc, float alpha, int dv,
    long sAhi, long sAlo, long sBhi, long sBlo, long sChi, long sClo) {
    const int BM = 64, BN = 64, BK = 16;
    __shared__ __align__(16) float As[BK][BM + 4];  // transposed A tile: As[k][m]
    __shared__ __align__(16) float Bs[BK][BN + 4];  // Bs[k][n]

    int z = blockIdx.z;
    A += (long)(z / dv) * sAhi + (long)(z % dv) * sAlo;
    B += (long)(z / dv) * sBhi + (long)(z % dv) * sBlo;
    C += (long)(z / dv) * sChi + (long)(z % dv) * sClo;

    int m0 = blockIdx.y * BM, n0 = blockIdx.x * BN;
    int tid = threadIdx.x;
    int tx = tid & 15, ty = tid >> 4;

    float acc[4][4] = {};

    for (int k0 = 0; k0 < K; k0 += BK) {
        // A tile: A[m0+r][k0+c] -> As[c][r]
        #pragma unroll
        for (int rep = 0; rep < 4; rep++) {
            int idx = rep * 256 + tid;
            int r = idx >> 4, c = idx & 15;
            As[c][r] = A[(long)(m0 + r) * lda + (k0 + c)];
        }
        if (!TB) {
            #pragma unroll
            for (int rep = 0; rep < 4; rep++) {
                int idx = rep * 256 + tid;
                int r = idx >> 6, c = idx & 63;
                Bs[r][c] = B[(long)(k0 + r) * ldb + (n0 + c)];
            }
        } else {
            #pragma unroll
            for (int rep = 0; rep < 4; rep++) {
                int idx = rep * 256 + tid;
                int n = idx >> 4, kk = idx & 15;
                Bs[kk][n] = B[(long)(n0 + n) * ldb + (k0 + kk)];
            }
        }
        __syncthreads();

        #pragma unroll
        for (int k = 0; k < BK; k++) {
            float4 a4 = *reinterpret_cast<const float4*>(&As[k][ty * 4]);
            float4 b4 = *reinterpret_cast<const float4*>(&Bs[k][tx * 4]);
            float av[4] = {a4.x, a4.y, a4.z, a4.w};
            float bv[4] = {b4.x, b4.y, b4.z, b4.w};
            #pragma unroll
            for (int i = 0; i < 4; i++)
                #pragma unroll
                for (int j = 0; j < 4; j++)
                    acc[i][j] += av[i] * bv[j];
        }
        __syncthreads();
    }

    #pragma unroll
    for (int i = 0; i < 4; i++)
        #pragma unroll
        for (int j = 0; j < 4; j++)
            C[(long)(m0 + ty * 4 + i) * ldc + (n0 + tx * 4 + j)] = alpha * acc[i][j];
}

// ---------------- block reductions ----------------
__device__ __forceinline__ float blockReduceMax(float v, float* red) {
    #pragma unroll
    for (int o = 16; o > 0; o >>= 1) v = fmaxf(v, __shfl_xor_sync(0xFFFFFFFFu, v, o));
    int w = threadIdx.x >> 5, lane = threadIdx.x & 31;
    __syncthreads();
    if (lane == 0) red[w] = v;
    __syncthreads();
    v = (lane < (blockDim.x >> 5)) ? red[lane] : -F32_INF;
    #pragma unroll
    for (int o = 16; o > 0; o >>= 1) v = fmaxf(v, __shfl_xor_sync(0xFFFFFFFFu, v, o));
    return v;
}
__device__ __forceinline__ float blockReduceMin(float v, float* red) {
    #pragma unroll
    for (int o = 16; o > 0; o >>= 1) v = fminf(v, __shfl_xor_sync(0xFFFFFFFFu, v, o));
    int w = threadIdx.x >> 5, lane = threadIdx.x & 31;
    __syncthreads();
    if (lane == 0) red[w] = v;
    __syncthreads();
    v = (lane < (blockDim.x >> 5)) ? red[lane] : F32_INF;
    #pragma unroll
    for (int o = 16; o > 0; o >>= 1) v = fminf(v, __shfl_xor_sync(0xFFFFFFFFu, v, o));
    return v;
}
__device__ __forceinline__ float blockReduceSum(float v, float* red) {
    #pragma unroll
    for (int o = 16; o > 0; o >>= 1) v += __shfl_xor_sync(0xFFFFFFFFu, v, o);
    int w = threadIdx.x >> 5, lane = threadIdx.x & 31;
    __syncthreads();
    if (lane == 0) red[w] = v;
    __syncthreads();
    v = (lane < (blockDim.x >> 5)) ? red[lane] : 0.f;
    #pragma unroll
    for (int o = 16; o > 0; o >>= 1) v += __shfl_xor_sync(0xFFFFFFFFu, v, o);
    return v;
}

// ---------------- softmax + differential + min-shift; writes final diff ----------------
__global__ __launch_bounds__(256) void softmax_diff_kernel(
    const void* __restrict__ qmask, const void* __restrict__ kmask,
    float* __restrict__ out_diff) {
    __shared__ float p1[NL];   // 16 KB
    __shared__ float p2[NL];   // 16 KB
    __shared__ float red[32];

    int bs = blockIdx.x;                 // b*512 + s
    int b = bs >> 9;
    int s = bs & 511;
    int tid = threadIdx.x;
    int mode = g_mask_mode;

    bool qm = mask_at(qmask, bs, mode);
    const float* s1 = g_S + ((long)(b * 2 + 0) * NS + s) * NL;
    const float* s2 = g_S + ((long)(b * 2 + 1) * NS + s) * NL;
    long kmbase = (long)b * NL;

    float m1 = -F32_INF, m2 = -F32_INF;
    for (int l = tid; l < NL; l += 256) {
        bool mk = qm && mask_at(kmask, kmbase + l, mode);
        float v1 = mk ? s1[l] : -1e20f;
        float v2 = mk ? s2[l] : -1e20f;
        p1[l] = v1; p2[l] = v2;
        m1 = fmaxf(m1, v1); m2 = fmaxf(m2, v2);
    }
    m1 = blockReduceMax(m1, red);
    m2 = blockReduceMax(m2, red);

    float sum1 = 0.f, sum2 = 0.f;
    for (int l = tid; l < NL; l += 256) {
        float e1 = expf(p1[l] - m1);
        float e2 = expf(p2[l] - m2);
        p1[l] = e1; p2[l] = e2;
        sum1 += e1; sum2 += e2;
    }
    sum1 = blockReduceSum(sum1, red);
    sum2 = blockReduceSum(sum2, red);
    float inv1 = 1.f / (sum1 + 1e-8f);
    float inv2 = 1.f / (sum2 + 1e-8f);
    float lam = g_lambda;

    float mn = F32_INF;
    for (int l = tid; l < NL; l += 256) {
        float d = p1[l] * inv1 - lam * (p2[l] * inv2);
        p1[l] = d;
        mn = fminf(mn, d);
    }
    mn = blockReduceMin(mn, red);

    float* od = out_diff + (long)bs * NL;
    for (int l = tid; l < NL; l += 256) {
        bool mk = qm && mask_at(kmask, kmbase + l, mode);
        od[l] = mk ? (p1[l] - mn + 1e-20f) : 0.f;
    }
}

// ---------------- RMS norm ----------------
__global__ __launch_bounds__(256) void rmsnorm_kernel(const float* __restrict__ ln) {
    __shared__ float red[32];
    int row = blockIdx.x;
    int tid = threadIdx.x;
    const float* a = g_AO + (long)row * NE;
    float ss = 0.f;
    for (int e = tid; e < NE; e += 256) { float v = a[e]; ss += v * v; }
    ss = blockReduceSum(ss, red);
    float scale = rsqrtf(ss / (float)NE + 1e-5f) * (1.0f - LAMBDA_INIT);
    float* x = g_X + (long)row * NE;
    for (int e = tid; e < NE; e += 256) x[e] = a[e] * scale * ln[e];
}

// ---------------- launch ----------------
extern "C" void kernel_launch(void* const* d_in, const int* in_sizes, int n_in,
                              void* d_out, int out_size) {
    const float* query = (const float*)d_in[0];   // (8,512,768)
    const float* key   = (const float*)d_in[1];   // (8,64,64,32) -> (8,4096,32)
    const void*  qmask = d_in[2];                 // (8,512) bool -> detected dtype
    const void*  kmask = d_in[3];                 // (8,64,64) bool -> detected dtype
    const float* Wq   = (const float*)d_in[4];    // (768,768)
    const float* Wkv  = (const float*)d_in[5];    // (32,1536)
    const float* Wout = (const float*)d_in[6];    // (768,768)
    const float* lq1  = (const float*)d_in[7];
    const float* lk1  = (const float*)d_in[8];
    const float* lq2  = (const float*)d_in[9];
    const float* lk2  = (const float*)d_in[10];
    const float* ln   = (const float*)d_in[11];

    float* outp = (float*)d_out;                       // (8,512,768)
    float* diffp = outp + (long)NB * NS * NE;          // (8,512,64,64)

    float *pQ, *pKV, *pS, *pAO, *pX;
    cudaGetSymbolAddress((void**)&pQ,  g_Q);
    cudaGetSymbolAddress((void**)&pKV, g_KV);
    cudaGetSymbolAddress((void**)&pS,  g_S);
    cudaGetSymbolAddress((void**)&pAO, g_AO);
    cudaGetSymbolAddress((void**)&pX,  g_X);

    // mask dtype detection + lambda scalar
    detect_mask_kernel<<<1, 256>>>((const unsigned char*)kmask);
    lambda_kernel<<<1, 384>>>(lq1, lk1, lq2, lk2);

    // Q = query @ Wq   : M=4096, N=768, K=768
    gemm_kernel<false><<<dim3(NE / 64, (NB * NS) / 64, 1), 256>>>(
        query, Wq, pQ, NB * NS, NE, NE, NE, NE, NE, 1.0f,
        1, 0, 0, 0, 0, 0, 0);

    // KV = key_flat @ Wkv : M=32768, N=1536, K=32
    gemm_kernel<false><<<dim3((2 * NE) / 64, (NB * NL) / 64, 1), 256>>>(
        key, Wkv, pKV, NB * NL, 2 * NE, NGE, NGE, 2 * NE, 2 * NE, 1.0f,
        1, 0, 0, 0, 0, 0, 0);

    // scores[z=(b,h)] = SCALING * Qh @ Kh^T : M=512, N=4096, K=384, 16 batches
    gemm_kernel<true><<<dim3(NL / 64, NS / 64, NB * 2), 256>>>(
        pQ, pKV, pS, NS, NL, NHD, NE, 2 * NE, NL, SCALING,
        2,
        (long)NS * NE, (long)NHD,                 // A: b -> +512*768, h -> +384
        (long)NL * 2 * NE, (long)NHD,             // B(K): b -> +4096*1536, h -> +384
        (long)2 * NS * NL, (long)NS * NL);        // C: b -> +2*512*4096, h -> +512*4096

    // softmax + diff + min-shift -> d_out diff region
    softmax_diff_kernel<<<NB * NS, 256>>>(qmask, kmask, diffp);

    // attn_out[b] = diff[b] @ V[b] : M=512, N=768, K=4096, 8 batches
    gemm_kernel<false><<<dim3(NE / 64, NS / 64, NB), 256>>>(
        diffp, pKV + NE, pAO, NS, NE, NL, NL, 2 * NE, NE, 1.0f,
        1,
        (long)NS * NL, 0,
        (long)NL * 2 * NE, 0,
        (long)NS * NE, 0);

    // RMS norm (+ *0.8 * ln_weight)
    rmsnorm_kernel<<<NB * NS, 256>>>(ln);

    // out = X @ Wout : M=4096, N=768, K=768
    gemm_kernel<false><<<dim3(NE / 64, (NB * NS) / 64, 1), 256>>>(
        pX, Wout, outp, NB * NS, NE, NE, NE, NE, NE, 1.0f,
        1, 0, 0, 0, 0, 0, 0);
}

// round 7
// speedup vs baseline: 1.6680x; 1.6680x over previous
#include <cuda_runtime.h>
#include <math.h>
#include <stdint.h>

#define F32_INF __int_as_float(0x7f800000)

// ---------------- problem constants ----------------
#define NB 8
#define NS 512
#define NE 768
#define NGE 32
#define NHD 384
#define NL 4096
#define LAMBDA_INIT 0.2f
#define SCALING 0.05103103630798287f   // 384^-0.5

// ---------------- scratch (__device__ globals; no allocation allowed) ----------------
__device__ float g_Q[NB * NS * NE];                      // 12.6 MB
__device__ float g_KV[(size_t)NB * NL * 2 * NE];         // 201 MB  (K | V, ld=1536)
__device__ float g_S[(size_t)NB * 2 * NS * NL];          // 134 MB  raw scores
__device__ float g_AO[NB * NS * NE];
__device__ float g_X[NB * NS * NE];
__device__ float g_lambda;
__device__ int   g_mask_mode;                            // 0=uint8, 1=int32, 2=float32

// ---------------- mask dtype detection ----------------
__global__ void detect_mask_kernel(const unsigned char* __restrict__ km) {
    __shared__ int s_non01, s_nonmult4;
    if (threadIdx.x == 0) { s_non01 = 0; s_nonmult4 = 0; }
    __syncthreads();
    int non01 = 0, nm4 = 0;
    for (int i = threadIdx.x; i < 32768; i += 256) {
        unsigned char v = km[i];
        if (v > 1) non01 = 1;
        if (v != 0 && (i & 3) != 0) nm4 = 1;
    }
    if (non01) atomicOr(&s_non01, 1);
    if (nm4)   atomicOr(&s_nonmult4, 1);
    __syncthreads();
    if (threadIdx.x == 0)
        g_mask_mode = s_non01 ? 2 : (s_nonmult4 ? 0 : 1);
}

__device__ __forceinline__ bool mask_at(const void* p, long idx, int mode) {
    if (mode == 1) return ((const int*)p)[idx] != 0;
    if (mode == 2) return ((const float*)p)[idx] != 0.0f;
    return ((const unsigned char*)p)[idx] != 0;
}

// ---------------- lambda scalar ----------------
__global__ void lambda_kernel(const float* __restrict__ lq1, const float* __restrict__ lk1,
                              const float* __restrict__ lq2, const float* __restrict__ lk2) {
    __shared__ float red1[12], red2[12];
    int t = threadIdx.x;  // 384 threads
    float a = lq1[t] * lk1[t];
    float b = lq2[t] * lk2[t];
    #pragma unroll
    for (int o = 16; o > 0; o >>= 1) {
        a += __shfl_xor_sync(0xFFFFFFFFu, a, o);
        b += __shfl_xor_sync(0xFFFFFFFFu, b, o);
    }
    if ((t & 31) == 0) { red1[t >> 5] = a; red2[t >> 5] = b; }
    __syncthreads();
    if (t == 0) {
        float s1 = 0.f, s2 = 0.f;
        for (int i = 0; i < 12; i++) { s1 += red1[i]; s2 += red2[i]; }
        g_lambda = expf(s1) - expf(s2) + LAMBDA_INIT;
    }
}

// ---------------- tf32 helpers ----------------
__device__ __forceinline__ float to_tf32(float x) {
    uint32_t r;
    asm("cvt.rna.tf32.f32 %0, %1;" : "=r"(r) : "f"(x));
    return __uint_as_float(r);
}
__device__ __forceinline__ void mma_tf32(float* d, const uint32_t* a, const uint32_t* b) {
    asm volatile(
        "mma.sync.aligned.m16n8k8.row.col.f32.tf32.tf32.f32 "
        "{%0,%1,%2,%3}, {%4,%5,%6,%7}, {%8,%9}, {%0,%1,%2,%3};"
        : "+f"(d[0]), "+f"(d[1]), "+f"(d[2]), "+f"(d[3])
        : "r"(a[0]), "r"(a[1]), "r"(a[2]), "r"(a[3]), "r"(b[0]), "r"(b[1]));
}

// ---------------- tensor-core tf32 GEMM ----------------
// C[M,N] = alpha * A[M,K] @ (TB ? B[N,K]^T : B[K,N])
// BM=BN=128, BK=16, 256 threads (8 warps of 32x64 warp tiles).
// Requires M%128==0, N%128==0, K%16==0 (true at all call sites).
template <bool TB>
__global__ __launch_bounds__(256) void mma_gemm(
    const float* __restrict__ A, const float* __restrict__ B, float* __restrict__ C,
    int M, int N, int K, int lda, int ldb, int ldc, float alpha, int dv,
    long sAhi, long sAlo, long sBhi, long sBlo, long sChi, long sClo) {
    const int BM = 128, BN = 128, BK = 16;
    const int APITCH = BK + 4;                   // 20 floats
    const int BPITCH_NT = BK + 4;                // Bs[n][k]
    const int BPITCH_NN = BN + 8;                // Bs[k][n]
    __shared__ __align__(16) float As[BM * APITCH];
    __shared__ __align__(16) float Bs[TB ? BN * BPITCH_NT : BK * BPITCH_NN];

    int z = blockIdx.z;
    A += (long)(z / dv) * sAhi + (long)(z % dv) * sAlo;
    B += (long)(z / dv) * sBhi + (long)(z % dv) * sBlo;
    C += (long)(z / dv) * sChi + (long)(z % dv) * sClo;

    int m0 = blockIdx.y * BM, n0 = blockIdx.x * BN;
    int tid = threadIdx.x;
    int warp = tid >> 5, lane = tid & 31;
    int g = lane >> 2, tg = lane & 3;
    int wm = (warp & 3) * 32, wn = (warp >> 2) * 64;

    float acc[2][8][4] = {};

    for (int k0 = 0; k0 < K; k0 += BK) {
        // ---- A tile: 128x16, 512 float4, 2 per thread ----
        #pragma unroll
        for (int rep = 0; rep < 2; rep++) {
            int idx = rep * 256 + tid;
            int r = idx >> 2, c4 = idx & 3;
            float4 v = *reinterpret_cast<const float4*>(&A[(long)(m0 + r) * lda + k0 + c4 * 4]);
            v.x = to_tf32(v.x); v.y = to_tf32(v.y); v.z = to_tf32(v.z); v.w = to_tf32(v.w);
            *reinterpret_cast<float4*>(&As[r * APITCH + c4 * 4]) = v;
        }
        // ---- B tile ----
        if (TB) {
            // B[N][K] row-major -> Bs[n][k]
            #pragma unroll
            for (int rep = 0; rep < 2; rep++) {
                int idx = rep * 256 + tid;
                int r = idx >> 2, c4 = idx & 3;
                float4 v = *reinterpret_cast<const float4*>(&B[(long)(n0 + r) * ldb + k0 + c4 * 4]);
                v.x = to_tf32(v.x); v.y = to_tf32(v.y); v.z = to_tf32(v.z); v.w = to_tf32(v.w);
                *reinterpret_cast<float4*>(&Bs[r * BPITCH_NT + c4 * 4]) = v;
            }
        } else {
            // B[K][N] row-major -> Bs[k][n]
            #pragma unroll
            for (int rep = 0; rep < 2; rep++) {
                int idx = rep * 256 + tid;
                int r = idx >> 5, c4 = idx & 31;
                float4 v = *reinterpret_cast<const float4*>(&B[(long)(k0 + r) * ldb + n0 + c4 * 4]);
                v.x = to_tf32(v.x); v.y = to_tf32(v.y); v.z = to_tf32(v.z); v.w = to_tf32(v.w);
                *reinterpret_cast<float4*>(&Bs[r * BPITCH_NN + c4 * 4]) = v;
            }
        }
        __syncthreads();

        #pragma unroll
        for (int kk = 0; kk < BK; kk += 8) {
            uint32_t af[2][4], bf[8][2];
            #pragma unroll
            for (int m = 0; m < 2; m++) {
                int row = wm + m * 16;
                af[m][0] = __float_as_uint(As[(row + g)     * APITCH + kk + tg]);
                af[m][1] = __float_as_uint(As[(row + g + 8) * APITCH + kk + tg]);
                af[m][2] = __float_as_uint(As[(row + g)     * APITCH + kk + tg + 4]);
                af[m][3] = __float_as_uint(As[(row + g + 8) * APITCH + kk + tg + 4]);
            }
            #pragma unroll
            for (int n = 0; n < 8; n++) {
                int col = wn + n * 8 + g;
                if (TB) {
                    bf[n][0] = __float_as_uint(Bs[col * BPITCH_NT + kk + tg]);
                    bf[n][1] = __float_as_uint(Bs[col * BPITCH_NT + kk + tg + 4]);
                } else {
                    bf[n][0] = __float_as_uint(Bs[(kk + tg)     * BPITCH_NN + col]);
                    bf[n][1] = __float_as_uint(Bs[(kk + tg + 4) * BPITCH_NN + col]);
                }
            }
            #pragma unroll
            for (int m = 0; m < 2; m++)
                #pragma unroll
                for (int n = 0; n < 8; n++)
                    mma_tf32(acc[m][n], af[m], bf[n]);
        }
        __syncthreads();
    }

    // ---- epilogue ----
    #pragma unroll
    for (int m = 0; m < 2; m++) {
        #pragma unroll
        for (int n = 0; n < 8; n++) {
            int row = m0 + wm + m * 16 + g;
            int col = n0 + wn + n * 8 + tg * 2;
            float2 v0 = make_float2(alpha * acc[m][n][0], alpha * acc[m][n][1]);
            float2 v1 = make_float2(alpha * acc[m][n][2], alpha * acc[m][n][3]);
            *reinterpret_cast<float2*>(&C[(long)row * ldc + col]) = v0;
            *reinterpret_cast<float2*>(&C[(long)(row + 8) * ldc + col]) = v1;
        }
    }
}

// ---------------- block reductions ----------------
__device__ __forceinline__ float blockReduceMax(float v, float* red) {
    #pragma unroll
    for (int o = 16; o > 0; o >>= 1) v = fmaxf(v, __shfl_xor_sync(0xFFFFFFFFu, v, o));
    int w = threadIdx.x >> 5, lane = threadIdx.x & 31;
    __syncthreads();
    if (lane == 0) red[w] = v;
    __syncthreads();
    v = (lane < (blockDim.x >> 5)) ? red[lane] : -F32_INF;
    #pragma unroll
    for (int o = 16; o > 0; o >>= 1) v = fmaxf(v, __shfl_xor_sync(0xFFFFFFFFu, v, o));
    return v;
}
__device__ __forceinline__ float blockReduceMin(float v, float* red) {
    #pragma unroll
    for (int o = 16; o > 0; o >>= 1) v = fminf(v, __shfl_xor_sync(0xFFFFFFFFu, v, o));
    int w = threadIdx.x >> 5, lane = threadIdx.x & 31;
    __syncthreads();
    if (lane == 0) red[w] = v;
    __syncthreads();
    v = (lane < (blockDim.x >> 5)) ? red[lane] : F32_INF;
    #pragma unroll
    for (int o = 16; o > 0; o >>= 1) v = fminf(v, __shfl_xor_sync(0xFFFFFFFFu, v, o));
    return v;
}
__device__ __forceinline__ float blockReduceSum(float v, float* red) {
    #pragma unroll
    for (int o = 16; o > 0; o >>= 1) v += __shfl_xor_sync(0xFFFFFFFFu, v, o);
    int w = threadIdx.x >> 5, lane = threadIdx.x & 31;
    __syncthreads();
    if (lane == 0) red[w] = v;
    __syncthreads();
    v = (lane < (blockDim.x >> 5)) ? red[lane] : 0.f;
    #pragma unroll
    for (int o = 16; o > 0; o >>= 1) v += __shfl_xor_sync(0xFFFFFFFFu, v, o);
    return v;
}

// ---------------- softmax + differential + min-shift ----------------
__global__ __launch_bounds__(256) void softmax_diff_kernel(
    const void* __restrict__ qmask, const void* __restrict__ kmask,
    float* __restrict__ out_diff) {
    __shared__ float p1[NL];
    __shared__ float p2[NL];
    __shared__ float red[32];

    int bs = blockIdx.x;
    int b = bs >> 9;
    int s = bs & 511;
    int tid = threadIdx.x;
    int mode = g_mask_mode;

    bool qm = mask_at(qmask, bs, mode);
    const float* s1 = g_S + ((long)(b * 2 + 0) * NS + s) * NL;
    const float* s2 = g_S + ((long)(b * 2 + 1) * NS + s) * NL;
    long kmbase = (long)b * NL;

    float m1 = -F32_INF, m2 = -F32_INF;
    for (int l = tid; l < NL; l += 256) {
        bool mk = qm && mask_at(kmask, kmbase + l, mode);
        float v1 = mk ? s1[l] : -1e20f;
        float v2 = mk ? s2[l] : -1e20f;
        p1[l] = v1; p2[l] = v2;
        m1 = fmaxf(m1, v1); m2 = fmaxf(m2, v2);
    }
    m1 = blockReduceMax(m1, red);
    m2 = blockReduceMax(m2, red);

    float sum1 = 0.f, sum2 = 0.f;
    for (int l = tid; l < NL; l += 256) {
        float e1 = expf(p1[l] - m1);
        float e2 = expf(p2[l] - m2);
        p1[l] = e1; p2[l] = e2;
        sum1 += e1; sum2 += e2;
    }
    sum1 = blockReduceSum(sum1, red);
    sum2 = blockReduceSum(sum2, red);
    float inv1 = 1.f / (sum1 + 1e-8f);
    float inv2 = 1.f / (sum2 + 1e-8f);
    float lam = g_lambda;

    float mn = F32_INF;
    for (int l = tid; l < NL; l += 256) {
        float d = p1[l] * inv1 - lam * (p2[l] * inv2);
        p1[l] = d;
        mn = fminf(mn, d);
    }
    mn = blockReduceMin(mn, red);

    float* od = out_diff + (long)bs * NL;
    for (int l = tid; l < NL; l += 256) {
        bool mk = qm && mask_at(kmask, kmbase + l, mode);
        od[l] = mk ? (p1[l] - mn + 1e-20f) : 0.f;
    }
}

// ---------------- RMS norm ----------------
__global__ __launch_bounds__(256) void rmsnorm_kernel(const float* __restrict__ ln) {
    __shared__ float red[32];
    int row = blockIdx.x;
    int tid = threadIdx.x;
    const float* a = g_AO + (long)row * NE;
    float ss = 0.f;
    for (int e = tid; e < NE; e += 256) { float v = a[e]; ss += v * v; }
    ss = blockReduceSum(ss, red);
    float scale = rsqrtf(ss / (float)NE + 1e-5f) * (1.0f - LAMBDA_INIT);
    float* x = g_X + (long)row * NE;
    for (int e = tid; e < NE; e += 256) x[e] = a[e] * scale * ln[e];
}

// ---------------- launch ----------------
extern "C" void kernel_launch(void* const* d_in, const int* in_sizes, int n_in,
                              void* d_out, int out_size) {
    const float* query = (const float*)d_in[0];   // (8,512,768)
    const float* key   = (const float*)d_in[1];   // (8,64,64,32)
    const void*  qmask = d_in[2];                 // (8,512)
    const void*  kmask = d_in[3];                 // (8,64,64)
    const float* Wq   = (const float*)d_in[4];
    const float* Wkv  = (const float*)d_in[5];
    const float* Wout = (const float*)d_in[6];
    const float* lq1  = (const float*)d_in[7];
    const float* lk1  = (const float*)d_in[8];
    const float* lq2  = (const float*)d_in[9];
    const float* lk2  = (const float*)d_in[10];
    const float* ln   = (const float*)d_in[11];

    float* outp = (float*)d_out;                       // (8,512,768)
    float* diffp = outp + (long)NB * NS * NE;          // (8,512,64,64)

    float *pQ, *pKV, *pS, *pAO, *pX;
    cudaGetSymbolAddress((void**)&pQ,  g_Q);
    cudaGetSymbolAddress((void**)&pKV, g_KV);
    cudaGetSymbolAddress((void**)&pS,  g_S);
    cudaGetSymbolAddress((void**)&pAO, g_AO);
    cudaGetSymbolAddress((void**)&pX,  g_X);

    detect_mask_kernel<<<1, 256>>>((const unsigned char*)kmask);
    lambda_kernel<<<1, 384>>>(lq1, lk1, lq2, lk2);

    // Q = query @ Wq : M=4096, N=768, K=768
    mma_gemm<false><<<dim3(NE / 128, (NB * NS) / 128, 1), 256>>>(
        query, Wq, pQ, NB * NS, NE, NE, NE, NE, NE, 1.0f,
        1, 0, 0, 0, 0, 0, 0);

    // KV = key_flat @ Wkv : M=32768, N=1536, K=32
    mma_gemm<false><<<dim3((2 * NE) / 128, (NB * NL) / 128, 1), 256>>>(
        key, Wkv, pKV, NB * NL, 2 * NE, NGE, NGE, 2 * NE, 2 * NE, 1.0f,
        1, 0, 0, 0, 0, 0, 0);

    // scores = SCALING * Qh @ Kh^T : M=512, N=4096, K=384, 16 batches (b,h)
    mma_gemm<true><<<dim3(NL / 128, NS / 128, NB * 2), 256>>>(
        pQ, pKV, pS, NS, NL, NHD, NE, 2 * NE, NL, SCALING,
        2,
        (long)NS * NE, (long)NHD,
        (long)NL * 2 * NE, (long)NHD,
        (long)2 * NS * NL, (long)NS * NL);

    // softmax + diff + min-shift -> d_out diff region
    softmax_diff_kernel<<<NB * NS, 256>>>(qmask, kmask, diffp);

    // attn_out[b] = diff[b] @ V[b] : M=512, N=768, K=4096, 8 batches
    mma_gemm<false><<<dim3(NE / 128, NS / 128, NB), 256>>>(
        diffp, pKV + NE, pAO, NS, NE, NL, NL, 2 * NE, NE, 1.0f,
        1,
        (long)NS * NL, 0,
        (long)NL * 2 * NE, 0,
        (long)NS * NE, 0);

    // RMS norm
    rmsnorm_kernel<<<NB * NS, 256>>>(ln);

    // out = X @ Wout : M=4096, N=768, K=768
    mma_gemm<false><<<dim3(NE / 128, (NB * NS) / 128, 1), 256>>>(
        pX, Wout, outp, NB * NS, NE, NE, NE, NE, NE, 1.0f,
        1, 0, 0, 0, 0, 0, 0);
}

// round 8
// speedup vs baseline: 2.8711x; 1.7212x over previous
#include <cuda_runtime.h>
#include <math.h>
#include <stdint.h>

#define F32_INF __int_as_float(0x7f800000)

// ---------------- problem constants ----------------
#define NB 8
#define NS 512
#define NE 768
#define NGE 32
#define NHD 384
#define NL 4096
#define LAMBDA_INIT 0.2f
#define SCALING 0.05103103630798287f   // 384^-0.5

// ---------------- scratch ----------------
__device__ float g_Q[NB * NS * NE];
__device__ float g_KV[(size_t)NB * NL * 2 * NE];
__device__ float g_S[(size_t)NB * 2 * NS * NL];
__device__ float g_AO[NB * NS * NE];
__device__ float g_X[NB * NS * NE];
__device__ float g_lambda;
__device__ int   g_mask_mode;   // 0=uint8, 1=int32, 2=float32

// ---------------- cp.async helpers ----------------
__device__ __forceinline__ uint32_t smem_u32(const void* p) {
    return (uint32_t)__cvta_generic_to_shared(p);
}
#define CP_ASYNC16(dst, src) \
    asm volatile("cp.async.cg.shared.global [%0], [%1], 16;\n" :: "r"(dst), "l"(src))
#define CP_COMMIT() asm volatile("cp.async.commit_group;\n" ::)
#define CP_WAIT(N)  asm volatile("cp.async.wait_group %0;\n" :: "n"(N))

// ---------------- mask dtype detection ----------------
__global__ void detect_mask_kernel(const unsigned char* __restrict__ km) {
    __shared__ int s_non01, s_nonmult4;
    if (threadIdx.x == 0) { s_non01 = 0; s_nonmult4 = 0; }
    __syncthreads();
    int non01 = 0, nm4 = 0;
    for (int i = threadIdx.x; i < 32768; i += 256) {
        unsigned char v = km[i];
        if (v > 1) non01 = 1;
        if (v != 0 && (i & 3) != 0) nm4 = 1;
    }
    if (non01) atomicOr(&s_non01, 1);
    if (nm4)   atomicOr(&s_nonmult4, 1);
    __syncthreads();
    if (threadIdx.x == 0)
        g_mask_mode = s_non01 ? 2 : (s_nonmult4 ? 0 : 1);
}

__device__ __forceinline__ bool mask_at(const void* p, long idx, int mode) {
    if (mode == 1) return ((const int*)p)[idx] != 0;
    if (mode == 2) return ((const float*)p)[idx] != 0.0f;
    return ((const unsigned char*)p)[idx] != 0;
}

// ---------------- lambda scalar ----------------
__global__ void lambda_kernel(const float* __restrict__ lq1, const float* __restrict__ lk1,
                              const float* __restrict__ lq2, const float* __restrict__ lk2) {
    __shared__ float red1[12], red2[12];
    int t = threadIdx.x;
    float a = lq1[t] * lk1[t];
    float b = lq2[t] * lk2[t];
    #pragma unroll
    for (int o = 16; o > 0; o >>= 1) {
        a += __shfl_xor_sync(0xFFFFFFFFu, a, o);
        b += __shfl_xor_sync(0xFFFFFFFFu, b, o);
    }
    if ((t & 31) == 0) { red1[t >> 5] = a; red2[t >> 5] = b; }
    __syncthreads();
    if (t == 0) {
        float s1 = 0.f, s2 = 0.f;
        for (int i = 0; i < 12; i++) { s1 += red1[i]; s2 += red2[i]; }
        g_lambda = expf(s1) - expf(s2) + LAMBDA_INIT;
    }
}

// ---------------- tf32 helpers ----------------
__device__ __forceinline__ uint32_t to_tf32_u(float x) {
    uint32_t r;
    asm("cvt.rna.tf32.f32 %0, %1;" : "=r"(r) : "f"(x));
    return r;
}
__device__ __forceinline__ void mma_tf32(float* d, const uint32_t* a, const uint32_t* b) {
    asm volatile(
        "mma.sync.aligned.m16n8k8.row.col.f32.tf32.tf32.f32 "
        "{%0,%1,%2,%3}, {%4,%5,%6,%7}, {%8,%9}, {%0,%1,%2,%3};"
        : "+f"(d[0]), "+f"(d[1]), "+f"(d[2]), "+f"(d[3])
        : "r"(a[0]), "r"(a[1]), "r"(a[2]), "r"(a[3]), "r"(b[0]), "r"(b[1]));
}

// ---------------- tensor-core tf32 GEMM, 2-stage cp.async pipeline ----------------
// C[M,N] = alpha * A[M,K] @ (TB ? B[N,K]^T : B[K,N])
// BM=BN=128, BK=16, 256 threads (8 warps, 32x64 warp tiles).
// Requires M%128==0, N%128==0, K%32==0... actually K%16==0 (pipeline handles any #iters>=1).
template <bool TB>
__global__ __launch_bounds__(256) void mma_gemm(
    const float* __restrict__ A, const float* __restrict__ B, float* __restrict__ C,
    int M, int N, int K, int lda, int ldb, int ldc, float alpha, int dv,
    long sAhi, long sAlo, long sBhi, long sBlo, long sChi, long sClo) {
    const int BM = 128, BN = 128, BK = 16;
    const int APITCH = BK + 4;                   // 20 floats (80B, 16B-multiple)
    const int BPITCH_NT = BK + 4;                // 20 floats
    const int BPITCH_NN = BN + 8;                // 136 floats (544B, 16B-multiple)
    const int BSTG = TB ? BN * BPITCH_NT : BK * BPITCH_NN;
    __shared__ __align__(16) float As[2][BM * APITCH];
    __shared__ __align__(16) float Bs[2][BSTG];

    int z = blockIdx.z;
    A += (long)(z / dv) * sAhi + (long)(z % dv) * sAlo;
    B += (long)(z / dv) * sBhi + (long)(z % dv) * sBlo;
    C += (long)(z / dv) * sChi + (long)(z % dv) * sClo;

    int m0 = blockIdx.y * BM, n0 = blockIdx.x * BN;
    int tid = threadIdx.x;
    int warp = tid >> 5, lane = tid & 31;
    int g = lane >> 2, tg = lane & 3;
    int wm = (warp & 3) * 32, wn = (warp >> 2) * 64;

    // per-thread load coordinates (2 x float4 for A, 2 for B per stage)
    int ar[2], ac[2], br[2], bc[2];
    #pragma unroll
    for (int rep = 0; rep < 2; rep++) {
        int idx = rep * 256 + tid;
        ar[rep] = idx >> 2; ac[rep] = (idx & 3) * 4;          // A: row 0..127, col 0/4/8/12
        if (TB) { br[rep] = idx >> 2; bc[rep] = (idx & 3) * 4; }     // B rows=n
        else    { br[rep] = idx >> 5; bc[rep] = (idx & 31) * 4; }    // B rows=k, col 0..124
    }

    int niter = K / BK;

    // ---- prefetch stage 0 ----
    {
        #pragma unroll
        for (int rep = 0; rep < 2; rep++) {
            CP_ASYNC16(smem_u32(&As[0][ar[rep] * APITCH + ac[rep]]),
                       &A[(long)(m0 + ar[rep]) * lda + ac[rep]]);
            if (TB)
                CP_ASYNC16(smem_u32(&Bs[0][br[rep] * BPITCH_NT + bc[rep]]),
                           &B[(long)(n0 + br[rep]) * ldb + bc[rep]]);
            else
                CP_ASYNC16(smem_u32(&Bs[0][br[rep] * BPITCH_NN + bc[rep]]),
                           &B[(long)br[rep] * ldb + n0 + bc[rep]]);
        }
        CP_COMMIT();
    }

    float acc[2][8][4] = {};

    for (int it = 0; it < niter; it++) {
        int cur = it & 1;
        // ---- prefetch next stage ----
        if (it + 1 < niter) {
            int nxt = (it + 1) & 1;
            int k0 = (it + 1) * BK;
            #pragma unroll
            for (int rep = 0; rep < 2; rep++) {
                CP_ASYNC16(smem_u32(&As[nxt][ar[rep] * APITCH + ac[rep]]),
                           &A[(long)(m0 + ar[rep]) * lda + k0 + ac[rep]]);
                if (TB)
                    CP_ASYNC16(smem_u32(&Bs[nxt][br[rep] * BPITCH_NT + bc[rep]]),
                               &B[(long)(n0 + br[rep]) * ldb + k0 + bc[rep]]);
                else
                    CP_ASYNC16(smem_u32(&Bs[nxt][(long)br[rep] * BPITCH_NN + bc[rep]]),
                               &B[(long)(k0 + br[rep]) * ldb + n0 + bc[rep]]);
            }
            CP_COMMIT();
            CP_WAIT(1);
        } else {
            CP_WAIT(0);
        }
        __syncthreads();

        const float* Asc = As[cur];
        const float* Bsc = Bs[cur];
        #pragma unroll
        for (int kk = 0; kk < BK; kk += 8) {
            uint32_t af[2][4], bf[8][2];
            #pragma unroll
            for (int m = 0; m < 2; m++) {
                int row = wm + m * 16;
                af[m][0] = to_tf32_u(Asc[(row + g)     * APITCH + kk + tg]);
                af[m][1] = to_tf32_u(Asc[(row + g + 8) * APITCH + kk + tg]);
                af[m][2] = to_tf32_u(Asc[(row + g)     * APITCH + kk + tg + 4]);
                af[m][3] = to_tf32_u(Asc[(row + g + 8) * APITCH + kk + tg + 4]);
            }
            #pragma unroll
            for (int n = 0; n < 8; n++) {
                int col = wn + n * 8 + g;
                if (TB) {
                    bf[n][0] = to_tf32_u(Bsc[col * BPITCH_NT + kk + tg]);
                    bf[n][1] = to_tf32_u(Bsc[col * BPITCH_NT + kk + tg + 4]);
                } else {
                    bf[n][0] = to_tf32_u(Bsc[(kk + tg)     * BPITCH_NN + col]);
                    bf[n][1] = to_tf32_u(Bsc[(kk + tg + 4) * BPITCH_NN + col]);
                }
            }
            #pragma unroll
            for (int m = 0; m < 2; m++)
                #pragma unroll
                for (int n = 0; n < 8; n++)
                    mma_tf32(acc[m][n], af[m], bf[n]);
        }
        __syncthreads();   // protect cur buffer from next iteration's prefetch
    }

    // ---- epilogue ----
    #pragma unroll
    for (int m = 0; m < 2; m++) {
        #pragma unroll
        for (int n = 0; n < 8; n++) {
            int row = m0 + wm + m * 16 + g;
            int col = n0 + wn + n * 8 + tg * 2;
            float2 v0 = make_float2(alpha * acc[m][n][0], alpha * acc[m][n][1]);
            float2 v1 = make_float2(alpha * acc[m][n][2], alpha * acc[m][n][3]);
            *reinterpret_cast<float2*>(&C[(long)row * ldc + col]) = v0;
            *reinterpret_cast<float2*>(&C[(long)(row + 8) * ldc + col]) = v1;
        }
    }
}

// ---------------- block reductions ----------------
__device__ __forceinline__ float blockReduceMax(float v, float* red) {
    #pragma unroll
    for (int o = 16; o > 0; o >>= 1) v = fmaxf(v, __shfl_xor_sync(0xFFFFFFFFu, v, o));
    int w = threadIdx.x >> 5, lane = threadIdx.x & 31;
    __syncthreads();
    if (lane == 0) red[w] = v;
    __syncthreads();
    v = (lane < (blockDim.x >> 5)) ? red[lane] : -F32_INF;
    #pragma unroll
    for (int o = 16; o > 0; o >>= 1) v = fmaxf(v, __shfl_xor_sync(0xFFFFFFFFu, v, o));
    return v;
}
__device__ __forceinline__ float blockReduceMin(float v, float* red) {
    #pragma unroll
    for (int o = 16; o > 0; o >>= 1) v = fminf(v, __shfl_xor_sync(0xFFFFFFFFu, v, o));
    int w = threadIdx.x >> 5, lane = threadIdx.x & 31;
    __syncthreads();
    if (lane == 0) red[w] = v;
    __syncthreads();
    v = (lane < (blockDim.x >> 5)) ? red[lane] : F32_INF;
    #pragma unroll
    for (int o = 16; o > 0; o >>= 1) v = fminf(v, __shfl_xor_sync(0xFFFFFFFFu, v, o));
    return v;
}
__device__ __forceinline__ float blockReduceSum(float v, float* red) {
    #pragma unroll
    for (int o = 16; o > 0; o >>= 1) v += __shfl_xor_sync(0xFFFFFFFFu, v, o);
    int w = threadIdx.x >> 5, lane = threadIdx.x & 31;
    __syncthreads();
    if (lane == 0) red[w] = v;
    __syncthreads();
    v = (lane < (blockDim.x >> 5)) ? red[lane] : 0.f;
    #pragma unroll
    for (int o = 16; o > 0; o >>= 1) v += __shfl_xor_sync(0xFFFFFFFFu, v, o);
    return v;
}

// ---------------- softmax + differential + min-shift ----------------
__global__ __launch_bounds__(256) void softmax_diff_kernel(
    const void* __restrict__ qmask, const void* __restrict__ kmask,
    float* __restrict__ out_diff) {
    __shared__ float p1[NL];
    __shared__ float p2[NL];
    __shared__ float red[32];

    int bs = blockIdx.x;
    int b = bs >> 9;
    int s = bs & 511;
    int tid = threadIdx.x;
    int mode = g_mask_mode;

    bool qm = mask_at(qmask, bs, mode);
    const float* s1 = g_S + ((long)(b * 2 + 0) * NS + s) * NL;
    const float* s2 = g_S + ((long)(b * 2 + 1) * NS + s) * NL;
    long kmbase = (long)b * NL;

    float m1 = -F32_INF, m2 = -F32_INF;
    for (int l = tid; l < NL; l += 256) {
        bool mk = qm && mask_at(kmask, kmbase + l, mode);
        float v1 = mk ? s1[l] : -1e20f;
        float v2 = mk ? s2[l] : -1e20f;
        p1[l] = v1; p2[l] = v2;
        m1 = fmaxf(m1, v1); m2 = fmaxf(m2, v2);
    }
    m1 = blockReduceMax(m1, red);
    m2 = blockReduceMax(m2, red);

    float sum1 = 0.f, sum2 = 0.f;
    for (int l = tid; l < NL; l += 256) {
        float e1 = expf(p1[l] - m1);
        float e2 = expf(p2[l] - m2);
        p1[l] = e1; p2[l] = e2;
        sum1 += e1; sum2 += e2;
    }
    sum1 = blockReduceSum(sum1, red);
    sum2 = blockReduceSum(sum2, red);
    float inv1 = 1.f / (sum1 + 1e-8f);
    float inv2 = 1.f / (sum2 + 1e-8f);
    float lam = g_lambda;

    float mn = F32_INF;
    for (int l = tid; l < NL; l += 256) {
        float d = p1[l] * inv1 - lam * (p2[l] * inv2);
        p1[l] = d;
        mn = fminf(mn, d);
    }
    mn = blockReduceMin(mn, red);

    float* od = out_diff + (long)bs * NL;
    for (int l = tid; l < NL; l += 256) {
        bool mk = qm && mask_at(kmask, kmbase + l, mode);
        od[l] = mk ? (p1[l] - mn + 1e-20f) : 0.f;
    }
}

// ---------------- RMS norm ----------------
__global__ __launch_bounds__(256) void rmsnorm_kernel(const float* __restrict__ ln) {
    __shared__ float red[32];
    int row = blockIdx.x;
    int tid = threadIdx.x;
    const float* a = g_AO + (long)row * NE;
    float ss = 0.f;
    for (int e = tid; e < NE; e += 256) { float v = a[e]; ss += v * v; }
    ss = blockReduceSum(ss, red);
    float scale = rsqrtf(ss / (float)NE + 1e-5f) * (1.0f - LAMBDA_INIT);
    float* x = g_X + (long)row * NE;
    for (int e = tid; e < NE; e += 256) x[e] = a[e] * scale * ln[e];
}

// ---------------- launch ----------------
extern "C" void kernel_launch(void* const* d_in, const int* in_sizes, int n_in,
                              void* d_out, int out_size) {
    const float* query = (const float*)d_in[0];   // (8,512,768)
    const float* key   = (const float*)d_in[1];   // (8,64,64,32)
    const void*  qmask = d_in[2];                 // (8,512)
    const void*  kmask = d_in[3];                 // (8,64,64)
    const float* Wq   = (const float*)d_in[4];
    const float* Wkv  = (const float*)d_in[5];
    const float* Wout = (const float*)d_in[6];
    const float* lq1  = (const float*)d_in[7];
    const float* lk1  = (const float*)d_in[8];
    const float* lq2  = (const float*)d_in[9];
    const float* lk2  = (const float*)d_in[10];
    const float* ln   = (const float*)d_in[11];

    float* outp = (float*)d_out;                       // (8,512,768)
    float* diffp = outp + (long)NB * NS * NE;          // (8,512,64,64)

    float *pQ, *pKV, *pS, *pAO, *pX;
    cudaGetSymbolAddress((void**)&pQ,  g_Q);
    cudaGetSymbolAddress((void**)&pKV, g_KV);
    cudaGetSymbolAddress((void**)&pS,  g_S);
    cudaGetSymbolAddress((void**)&pAO, g_AO);
    cudaGetSymbolAddress((void**)&pX,  g_X);

    detect_mask_kernel<<<1, 256>>>((const unsigned char*)kmask);
    lambda_kernel<<<1, 384>>>(lq1, lk1, lq2, lk2);

    // Q = query @ Wq : M=4096, N=768, K=768
    mma_gemm<false><<<dim3(NE / 128, (NB * NS) / 128, 1), 256>>>(
        query, Wq, pQ, NB * NS, NE, NE, NE, NE, NE, 1.0f,
        1, 0, 0, 0, 0, 0, 0);

    // KV = key_flat @ Wkv : M=32768, N=1536, K=32
    mma_gemm<false><<<dim3((2 * NE) / 128, (NB * NL) / 128, 1), 256>>>(
        key, Wkv, pKV, NB * NL, 2 * NE, NGE, NGE, 2 * NE, 2 * NE, 1.0f,
        1, 0, 0, 0, 0, 0, 0);

    // scores = SCALING * Qh @ Kh^T : M=512, N=4096, K=384, 16 batches (b,h)
    mma_gemm<true><<<dim3(NL / 128, NS / 128, NB * 2), 256>>>(
        pQ, pKV, pS, NS, NL, NHD, NE, 2 * NE, NL, SCALING,
        2,
        (long)NS * NE, (long)NHD,
        (long)NL * 2 * NE, (long)NHD,
        (long)2 * NS * NL, (long)NS * NL);

    // softmax + diff + min-shift -> d_out diff region
    softmax_diff_kernel<<<NB * NS, 256>>>(qmask, kmask, diffp);

    // attn_out[b] = diff[b] @ V[b] : M=512, N=768, K=4096, 8 batches
    mma_gemm<false><<<dim3(NE / 128, NS / 128, NB), 256>>>(
        diffp, pKV + NE, pAO, NS, NE, NL, NL, 2 * NE, NE, 1.0f,
        1,
        (long)NS * NL, 0,
        (long)NL * 2 * NE, 0,
        (long)NS * NE, 0);

    // RMS norm
    rmsnorm_kernel<<<NB * NS, 256>>>(ln);

    // out = X @ Wout : M=4096, N=768, K=768
    mma_gemm<false><<<dim3(NE / 128, (NB * NS) / 128, 1), 256>>>(
        pX, Wout, outp, NB * NS, NE, NE, NE, NE, NE, 1.0f,
        1, 0, 0, 0, 0, 0, 0);
}

// round 9
// speedup vs baseline: 2.9522x; 1.0282x over previous
#include <cuda_runtime.h>
#include <math.h>
#include <stdint.h>

#define F32_INF __int_as_float(0x7f800000)

// ---------------- problem constants ----------------
#define NB 8
#define NS 512
#define NE 768
#define NGE 32
#define NHD 384
#define NL 4096
#define LAMBDA_INIT 0.2f
#define SCALING 0.05103103630798287f   // 384^-0.5
#define KSPLIT 4

// ---------------- scratch ----------------
__device__ float g_Q[NB * NS * NE];
__device__ float g_KV[(size_t)NB * NL * 2 * NE];
__device__ float g_S[(size_t)NB * 2 * NS * NL];
__device__ float g_P[(size_t)KSPLIT * NB * NS * NE];   // split-K partials for AV
__device__ float g_X[NB * NS * NE];
__device__ float g_lambda;
__device__ int   g_mask_mode;   // 0=uint8, 1=int32, 2=float32

// ---------------- cp.async helpers ----------------
__device__ __forceinline__ uint32_t smem_u32(const void* p) {
    return (uint32_t)__cvta_generic_to_shared(p);
}
#define CP_ASYNC16(dst, src) \
    asm volatile("cp.async.cg.shared.global [%0], [%1], 16;\n" :: "r"(dst), "l"(src))
#define CP_COMMIT() asm volatile("cp.async.commit_group;\n" ::)
#define CP_WAIT(N)  asm volatile("cp.async.wait_group %0;\n" :: "n"(N))

// ---------------- mask dtype detection ----------------
__global__ void detect_mask_kernel(const unsigned char* __restrict__ km) {
    __shared__ int s_non01, s_nonmult4;
    if (threadIdx.x == 0) { s_non01 = 0; s_nonmult4 = 0; }
    __syncthreads();
    int non01 = 0, nm4 = 0;
    for (int i = threadIdx.x; i < 32768; i += 256) {
        unsigned char v = km[i];
        if (v > 1) non01 = 1;
        if (v != 0 && (i & 3) != 0) nm4 = 1;
    }
    if (non01) atomicOr(&s_non01, 1);
    if (nm4)   atomicOr(&s_nonmult4, 1);
    __syncthreads();
    if (threadIdx.x == 0)
        g_mask_mode = s_non01 ? 2 : (s_nonmult4 ? 0 : 1);
}

__device__ __forceinline__ bool mask_at(const void* p, long idx, int mode) {
    if (mode == 1) return ((const int*)p)[idx] != 0;
    if (mode == 2) return ((const float*)p)[idx] != 0.0f;
    return ((const unsigned char*)p)[idx] != 0;
}

// ---------------- lambda scalar ----------------
__global__ void lambda_kernel(const float* __restrict__ lq1, const float* __restrict__ lk1,
                              const float* __restrict__ lq2, const float* __restrict__ lk2) {
    __shared__ float red1[12], red2[12];
    int t = threadIdx.x;
    float a = lq1[t] * lk1[t];
    float b = lq2[t] * lk2[t];
    #pragma unroll
    for (int o = 16; o > 0; o >>= 1) {
        a += __shfl_xor_sync(0xFFFFFFFFu, a, o);
        b += __shfl_xor_sync(0xFFFFFFFFu, b, o);
    }
    if ((t & 31) == 0) { red1[t >> 5] = a; red2[t >> 5] = b; }
    __syncthreads();
    if (t == 0) {
        float s1 = 0.f, s2 = 0.f;
        for (int i = 0; i < 12; i++) { s1 += red1[i]; s2 += red2[i]; }
        g_lambda = expf(s1) - expf(s2) + LAMBDA_INIT;
    }
}

// ---------------- tf32 helpers ----------------
__device__ __forceinline__ uint32_t to_tf32_u(float x) {
    uint32_t r;
    asm("cvt.rna.tf32.f32 %0, %1;" : "=r"(r) : "f"(x));
    return r;
}
__device__ __forceinline__ void mma_tf32(float* d, const uint32_t* a, const uint32_t* b) {
    asm volatile(
        "mma.sync.aligned.m16n8k8.row.col.f32.tf32.tf32.f32 "
        "{%0,%1,%2,%3}, {%4,%5,%6,%7}, {%8,%9}, {%0,%1,%2,%3};"
        : "+f"(d[0]), "+f"(d[1]), "+f"(d[2]), "+f"(d[3])
        : "r"(a[0]), "r"(a[1]), "r"(a[2]), "r"(a[3]), "r"(b[0]), "r"(b[1]));
}

// ---------------- tensor-core tf32 GEMM, 3-stage cp.async ring, 1 sync/iter ----------------
// C[M,N] = alpha * A[M,K] @ (TB ? B[N,K]^T : B[K,N])
// BM=BN=128, BK=16, 256 threads (8 warps, 32x64 warp tiles).
// Requires M%128==0, N%128==0, K%16==0, K/16 >= 2.
template <bool TB>
__global__ __launch_bounds__(256) void mma_gemm(
    const float* __restrict__ A, const float* __restrict__ B, float* __restrict__ C,
    int M, int N, int K, int lda, int ldb, int ldc, float alpha, int dv,
    long sAhi, long sAlo, long sBhi, long sBlo, long sChi, long sClo) {
    const int BM = 128, BN = 128, BK = 16;
    const int APITCH = BK + 4;                   // 20 floats
    const int BPITCH_NT = BK + 4;                // 20 floats
    const int BPITCH_NN = BN + 8;                // 136 floats
    const int BSTG = TB ? BN * BPITCH_NT : BK * BPITCH_NN;
    __shared__ __align__(16) float As[3][BM * APITCH];
    __shared__ __align__(16) float Bs[3][BSTG];

    int z = blockIdx.z;
    A += (long)(z / dv) * sAhi + (long)(z % dv) * sAlo;
    B += (long)(z / dv) * sBhi + (long)(z % dv) * sBlo;
    C += (long)(z / dv) * sChi + (long)(z % dv) * sClo;

    int m0 = blockIdx.y * BM, n0 = blockIdx.x * BN;
    int tid = threadIdx.x;
    int warp = tid >> 5, lane = tid & 31;
    int g = lane >> 2, tg = lane & 3;
    int wm = (warp & 3) * 32, wn = (warp >> 2) * 64;

    // per-thread load coordinates (2 x float4 for A, 2 for B per stage)
    int ar[2], ac[2], br[2], bc[2];
    #pragma unroll
    for (int rep = 0; rep < 2; rep++) {
        int idx = rep * 256 + tid;
        ar[rep] = idx >> 2; ac[rep] = (idx & 3) * 4;
        if (TB) { br[rep] = idx >> 2; bc[rep] = (idx & 3) * 4; }
        else    { br[rep] = idx >> 5; bc[rep] = (idx & 31) * 4; }
    }

    int niter = K / BK;

    // prefetch helper (issues the 4 cp.asyncs for stage `st` into buffer `buf`)
    auto prefetch = [&](int st, int buf) {
        int k0 = st * BK;
        #pragma unroll
        for (int rep = 0; rep < 2; rep++) {
            CP_ASYNC16(smem_u32(&As[buf][ar[rep] * APITCH + ac[rep]]),
                       &A[(long)(m0 + ar[rep]) * lda + k0 + ac[rep]]);
            if (TB)
                CP_ASYNC16(smem_u32(&Bs[buf][br[rep] * BPITCH_NT + bc[rep]]),
                           &B[(long)(n0 + br[rep]) * ldb + k0 + bc[rep]]);
            else
                CP_ASYNC16(smem_u32(&Bs[buf][br[rep] * BPITCH_NN + bc[rep]]),
                           &B[(long)(k0 + br[rep]) * ldb + n0 + bc[rep]]);
        }
    };

    // prologue: stages 0 and 1 (niter >= 2 at all call sites)
    prefetch(0, 0); CP_COMMIT();
    prefetch(1, 1); CP_COMMIT();

    float acc[2][8][4] = {};

    for (int it = 0; it < niter; it++) {
        int cur = it % 3;
        CP_WAIT(1);            // stage `it` complete (FIFO groups)
        __syncthreads();       // its smem writes visible to all; buffer (it-1)%3 free

        // prefetch stage it+2 into buffer (it+2)%3 == (it-1)%3
        if (it + 2 < niter) prefetch(it + 2, (it + 2) % 3);
        CP_COMMIT();           // commit (possibly empty) to keep group count aligned

        const float* Asc = As[cur];
        const float* Bsc = Bs[cur];
        #pragma unroll
        for (int kk = 0; kk < BK; kk += 8) {
            uint32_t af[2][4], bf[8][2];
            #pragma unroll
            for (int m = 0; m < 2; m++) {
                int row = wm + m * 16;
                af[m][0] = to_tf32_u(Asc[(row + g)     * APITCH + kk + tg]);
                af[m][1] = to_tf32_u(Asc[(row + g + 8) * APITCH + kk + tg]);
                af[m][2] = to_tf32_u(Asc[(row + g)     * APITCH + kk + tg + 4]);
                af[m][3] = to_tf32_u(Asc[(row + g + 8) * APITCH + kk + tg + 4]);
            }
            #pragma unroll
            for (int n = 0; n < 8; n++) {
                int col = wn + n * 8 + g;
                if (TB) {
                    bf[n][0] = to_tf32_u(Bsc[col * BPITCH_NT + kk + tg]);
                    bf[n][1] = to_tf32_u(Bsc[col * BPITCH_NT + kk + tg + 4]);
                } else {
                    bf[n][0] = to_tf32_u(Bsc[(kk + tg)     * BPITCH_NN + col]);
                    bf[n][1] = to_tf32_u(Bsc[(kk + tg + 4) * BPITCH_NN + col]);
                }
            }
            #pragma unroll
            for (int m = 0; m < 2; m++)
                #pragma unroll
                for (int n = 0; n < 8; n++)
                    mma_tf32(acc[m][n], af[m], bf[n]);
        }
    }

    // ---- epilogue ----
    #pragma unroll
    for (int m = 0; m < 2; m++) {
        #pragma unroll
        for (int n = 0; n < 8; n++) {
            int row = m0 + wm + m * 16 + g;
            int col = n0 + wn + n * 8 + tg * 2;
            float2 v0 = make_float2(alpha * acc[m][n][0], alpha * acc[m][n][1]);
            float2 v1 = make_float2(alpha * acc[m][n][2], alpha * acc[m][n][3]);
            *reinterpret_cast<float2*>(&C[(long)row * ldc + col]) = v0;
            *reinterpret_cast<float2*>(&C[(long)(row + 8) * ldc + col]) = v1;
        }
    }
}

// ---------------- block reductions ----------------
__device__ __forceinline__ float blockReduceMax(float v, float* red) {
    #pragma unroll
    for (int o = 16; o > 0; o >>= 1) v = fmaxf(v, __shfl_xor_sync(0xFFFFFFFFu, v, o));
    int w = threadIdx.x >> 5, lane = threadIdx.x & 31;
    __syncthreads();
    if (lane == 0) red[w] = v;
    __syncthreads();
    v = (lane < (blockDim.x >> 5)) ? red[lane] : -F32_INF;
    #pragma unroll
    for (int o = 16; o > 0; o >>= 1) v = fmaxf(v, __shfl_xor_sync(0xFFFFFFFFu, v, o));
    return v;
}
__device__ __forceinline__ float blockReduceMin(float v, float* red) {
    #pragma unroll
    for (int o = 16; o > 0; o >>= 1) v = fminf(v, __shfl_xor_sync(0xFFFFFFFFu, v, o));
    int w = threadIdx.x >> 5, lane = threadIdx.x & 31;
    __syncthreads();
    if (lane == 0) red[w] = v;
    __syncthreads();
    v = (lane < (blockDim.x >> 5)) ? red[lane] : F32_INF;
    #pragma unroll
    for (int o = 16; o > 0; o >>= 1) v = fminf(v, __shfl_xor_sync(0xFFFFFFFFu, v, o));
    return v;
}
__device__ __forceinline__ float blockReduceSum(float v, float* red) {
    #pragma unroll
    for (int o = 16; o > 0; o >>= 1) v += __shfl_xor_sync(0xFFFFFFFFu, v, o);
    int w = threadIdx.x >> 5, lane = threadIdx.x & 31;
    __syncthreads();
    if (lane == 0) red[w] = v;
    __syncthreads();
    v = (lane < (blockDim.x >> 5)) ? red[lane] : 0.f;
    #pragma unroll
    for (int o = 16; o > 0; o >>= 1) v += __shfl_xor_sync(0xFFFFFFFFu, v, o);
    return v;
}

// ---------------- softmax + differential + min-shift ----------------
__global__ __launch_bounds__(256) void softmax_diff_kernel(
    const void* __restrict__ qmask, const void* __restrict__ kmask,
    float* __restrict__ out_diff) {
    __shared__ float p1[NL];
    __shared__ float p2[NL];
    __shared__ float red[32];

    int bs = blockIdx.x;
    int b = bs >> 9;
    int s = bs & 511;
    int tid = threadIdx.x;
    int mode = g_mask_mode;

    bool qm = mask_at(qmask, bs, mode);
    const float* s1 = g_S + ((long)(b * 2 + 0) * NS + s) * NL;
    const float* s2 = g_S + ((long)(b * 2 + 1) * NS + s) * NL;
    long kmbase = (long)b * NL;

    float m1 = -F32_INF, m2 = -F32_INF;
    for (int l = tid; l < NL; l += 256) {
        bool mk = qm && mask_at(kmask, kmbase + l, mode);
        float v1 = mk ? s1[l] : -1e20f;
        float v2 = mk ? s2[l] : -1e20f;
        p1[l] = v1; p2[l] = v2;
        m1 = fmaxf(m1, v1); m2 = fmaxf(m2, v2);
    }
    m1 = blockReduceMax(m1, red);
    m2 = blockReduceMax(m2, red);

    float sum1 = 0.f, sum2 = 0.f;
    for (int l = tid; l < NL; l += 256) {
        float e1 = expf(p1[l] - m1);
        float e2 = expf(p2[l] - m2);
        p1[l] = e1; p2[l] = e2;
        sum1 += e1; sum2 += e2;
    }
    sum1 = blockReduceSum(sum1, red);
    sum2 = blockReduceSum(sum2, red);
    float inv1 = 1.f / (sum1 + 1e-8f);
    float inv2 = 1.f / (sum2 + 1e-8f);
    float lam = g_lambda;

    float mn = F32_INF;
    for (int l = tid; l < NL; l += 256) {
        float d = p1[l] * inv1 - lam * (p2[l] * inv2);
        p1[l] = d;
        mn = fminf(mn, d);
    }
    mn = blockReduceMin(mn, red);

    float* od = out_diff + (long)bs * NL;
    for (int l = tid; l < NL; l += 256) {
        bool mk = qm && mask_at(kmask, kmbase + l, mode);
        od[l] = mk ? (p1[l] - mn + 1e-20f) : 0.f;
    }
}

// ---------------- split-K reduce + RMS norm (fused) ----------------
__global__ __launch_bounds__(256) void rmsnorm_kernel(const float* __restrict__ ln) {
    __shared__ float red[32];
    __shared__ float row_buf[NE];
    int row = blockIdx.x;
    int tid = threadIdx.x;
    const long rbase = (long)row * NE;
    const long pstride = (long)NB * NS * NE;
    float ss = 0.f;
    for (int e = tid; e < NE; e += 256) {
        float v = g_P[rbase + e] + g_P[pstride + rbase + e]
                + g_P[2 * pstride + rbase + e] + g_P[3 * pstride + rbase + e];
        row_buf[e] = v;
        ss += v * v;
    }
    ss = blockReduceSum(ss, red);
    float scale = rsqrtf(ss / (float)NE + 1e-5f) * (1.0f - LAMBDA_INIT);
    float* x = g_X + rbase;
    for (int e = tid; e < NE; e += 256) x[e] = row_buf[e] * scale * ln[e];
}

// ---------------- launch ----------------
extern "C" void kernel_launch(void* const* d_in, const int* in_sizes, int n_in,
                              void* d_out, int out_size) {
    const float* query = (const float*)d_in[0];   // (8,512,768)
    const float* key   = (const float*)d_in[1];   // (8,64,64,32)
    const void*  qmask = d_in[2];                 // (8,512)
    const void*  kmask = d_in[3];                 // (8,64,64)
    const float* Wq   = (const float*)d_in[4];
    const float* Wkv  = (const float*)d_in[5];
    const float* Wout = (const float*)d_in[6];
    const float* lq1  = (const float*)d_in[7];
    const float* lk1  = (const float*)d_in[8];
    const float* lq2  = (const float*)d_in[9];
    const float* lk2  = (const float*)d_in[10];
    const float* ln   = (const float*)d_in[11];

    float* outp = (float*)d_out;                       // (8,512,768)
    float* diffp = outp + (long)NB * NS * NE;          // (8,512,64,64)

    float *pQ, *pKV, *pS, *pP, *pX;
    cudaGetSymbolAddress((void**)&pQ,  g_Q);
    cudaGetSymbolAddress((void**)&pKV, g_KV);
    cudaGetSymbolAddress((void**)&pS,  g_S);
    cudaGetSymbolAddress((void**)&pP,  g_P);
    cudaGetSymbolAddress((void**)&pX,  g_X);

    detect_mask_kernel<<<1, 256>>>((const unsigned char*)kmask);
    lambda_kernel<<<1, 384>>>(lq1, lk1, lq2, lk2);

    // Q = query @ Wq : M=4096, N=768, K=768
    mma_gemm<false><<<dim3(NE / 128, (NB * NS) / 128, 1), 256>>>(
        query, Wq, pQ, NB * NS, NE, NE, NE, NE, NE, 1.0f,
        1, 0, 0, 0, 0, 0, 0);

    // KV = key_flat @ Wkv : M=32768, N=1536, K=32
    mma_gemm<false><<<dim3((2 * NE) / 128, (NB * NL) / 128, 1), 256>>>(
        key, Wkv, pKV, NB * NL, 2 * NE, NGE, NGE, 2 * NE, 2 * NE, 1.0f,
        1, 0, 0, 0, 0, 0, 0);

    // scores = SCALING * Qh @ Kh^T : M=512, N=4096, K=384, 16 batches (b,h)
    mma_gemm<true><<<dim3(NL / 128, NS / 128, NB * 2), 256>>>(
        pQ, pKV, pS, NS, NL, NHD, NE, 2 * NE, NL, SCALING,
        2,
        (long)NS * NE, (long)NHD,
        (long)NL * 2 * NE, (long)NHD,
        (long)2 * NS * NL, (long)NS * NL);

    // softmax + diff + min-shift -> d_out diff region
    softmax_diff_kernel<<<NB * NS, 256>>>(qmask, kmask, diffp);

    // attn_out partials: diff[b][:, split*1024:(split+1)*1024] @ V-chunk
    // z = b*KSPLIT + split ; M=512, N=768, K=1024 per split ; 768 CTAs
    mma_gemm<false><<<dim3(NE / 128, NS / 128, NB * KSPLIT), 256>>>(
        diffp, pKV + NE, pP, NS, NE, NL / KSPLIT, NL, 2 * NE, NE, 1.0f,
        KSPLIT,
        (long)NS * NL, (long)(NL / KSPLIT),
        (long)NL * 2 * NE, (long)(NL / KSPLIT) * 2 * NE,
        (long)NS * NE, (long)NB * NS * NE);

    // split-K reduce + RMS norm
    rmsnorm_kernel<<<NB * NS, 256>>>(ln);

    // out = X @ Wout : M=4096, N=768, K=768
    mma_gemm<false><<<dim3(NE / 128, (NB * NS) / 128, 1), 256>>>(
        pX, Wout, outp, NB * NS, NE, NE, NE, NE, NE, 1.0f,
        1, 0, 0, 0, 0, 0, 0);
}

// round 12
// speedup vs baseline: 3.1668x; 1.0727x over previous
#include <cuda_runtime.h>
#include <math.h>
#include <stdint.h>

#define F32_INF __int_as_float(0x7f800000)

// ---------------- problem constants ----------------
#define NB 8
#define NS 512
#define NE 768
#define NGE 32
#define NHD 384
#define NL 4096
#define LAMBDA_INIT 0.2f
#define SCALING 0.05103103630798287f   // 384^-0.5
#define KSPLIT 4

// ---------------- scratch ----------------
__device__ float g_QI[NB * NS * NE];                    // tf32-rounded query input
__device__ float g_KI[NB * NL * NGE];                   // tf32-rounded key input
__device__ float g_W1[NE * NE];                         // tf32-rounded Wq
__device__ float g_W2[NGE * 2 * NE];                    // tf32-rounded Wkv
__device__ float g_W3[NE * NE];                         // tf32-rounded Wout
__device__ float g_Q[NB * NS * NE];                     // Q (tf32-rounded values)
__device__ float g_K[(size_t)NB * NL * NE];             // K (tf32-rounded, ld 768)
__device__ float g_V[(size_t)NB * NL * NE];             // V (tf32-rounded, ld 768)
__device__ float g_S[(size_t)NB * 2 * NS * NL];         // raw scores
__device__ float g_P[(size_t)KSPLIT * NB * NS * NE];    // split-K partials for AV
__device__ float g_X[NB * NS * NE];                     // normed (tf32-rounded)
__device__ float g_lambda;
__device__ int   g_mask_mode;   // 0=uint8, 1=int32, 2=float32

// ---------------- cp.async helpers ----------------
__device__ __forceinline__ uint32_t smem_u32(const void* p) {
    return (uint32_t)__cvta_generic_to_shared(p);
}
#define CP_ASYNC16(dst, src) \
    asm volatile("cp.async.cg.shared.global [%0], [%1], 16;\n" :: "r"(dst), "l"(src))
#define CP_COMMIT() asm volatile("cp.async.commit_group;\n" ::)
#define CP_WAIT(N)  asm volatile("cp.async.wait_group %0;\n" :: "n"(N))

// ---------------- tf32 helpers ----------------
__device__ __forceinline__ uint32_t to_tf32_u(float x) {
    uint32_t r;
    asm("cvt.rna.tf32.f32 %0, %1;" : "=r"(r) : "f"(x));
    return r;
}
__device__ __forceinline__ float to_tf32_f(float x) {
    return __uint_as_float(to_tf32_u(x));
}
__device__ __forceinline__ void mma_tf32(float* d, const uint32_t* a, const uint32_t* b) {
    asm volatile(
        "mma.sync.aligned.m16n8k8.row.col.f32.tf32.tf32.f32 "
        "{%0,%1,%2,%3}, {%4,%5,%6,%7}, {%8,%9}, {%0,%1,%2,%3};"
        : "+f"(d[0]), "+f"(d[1]), "+f"(d[2]), "+f"(d[3])
        : "r"(a[0]), "r"(a[1]), "r"(a[2]), "r"(a[3]), "r"(b[0]), "r"(b[1]));
}

// ---------------- pre-round inputs to tf32 ----------------
__global__ void round_tf32_kernel(const float* __restrict__ in, float* __restrict__ out, int n4) {
    int i = blockIdx.x * blockDim.x + threadIdx.x;
    if (i < n4) {
        float4 v = reinterpret_cast<const float4*>(in)[i];
        v.x = to_tf32_f(v.x); v.y = to_tf32_f(v.y);
        v.z = to_tf32_f(v.z); v.w = to_tf32_f(v.w);
        reinterpret_cast<float4*>(out)[i] = v;
    }
}

// ---------------- mask dtype detection ----------------
__global__ void detect_mask_kernel(const unsigned char* __restrict__ km) {
    __shared__ int s_non01, s_nonmult4;
    if (threadIdx.x == 0) { s_non01 = 0; s_nonmult4 = 0; }
    __syncthreads();
    int non01 = 0, nm4 = 0;
    for (int i = threadIdx.x; i < 32768; i += 256) {
        unsigned char v = km[i];
        if (v > 1) non01 = 1;
        if (v != 0 && (i & 3) != 0) nm4 = 1;
    }
    if (non01) atomicOr(&s_non01, 1);
    if (nm4)   atomicOr(&s_nonmult4, 1);
    __syncthreads();
    if (threadIdx.x == 0)
        g_mask_mode = s_non01 ? 2 : (s_nonmult4 ? 0 : 1);
}

__device__ __forceinline__ bool mask_at(const void* p, long idx, int mode) {
    if (mode == 1) return ((const int*)p)[idx] != 0;
    if (mode == 2) return ((const float*)p)[idx] != 0.0f;
    return ((const unsigned char*)p)[idx] != 0;
}

// ---------------- lambda scalar ----------------
__global__ void lambda_kernel(const float* __restrict__ lq1, const float* __restrict__ lk1,
                              const float* __restrict__ lq2, const float* __restrict__ lk2) {
    __shared__ float red1[12], red2[12];
    int t = threadIdx.x;
    float a = lq1[t] * lk1[t];
    float b = lq2[t] * lk2[t];
    #pragma unroll
    for (int o = 16; o > 0; o >>= 1) {
        a += __shfl_xor_sync(0xFFFFFFFFu, a, o);
        b += __shfl_xor_sync(0xFFFFFFFFu, b, o);
    }
    if ((t & 31) == 0) { red1[t >> 5] = a; red2[t >> 5] = b; }
    __syncthreads();
    if (t == 0) {
        float s1 = 0.f, s2 = 0.f;
        for (int i = 0; i < 12; i++) { s1 += red1[i]; s2 += red2[i]; }
        g_lambda = expf(s1) - expf(s2) + LAMBDA_INIT;
    }
}

// ---------------- tf32 GEMM, 3-stage cp.async ring, cvt-free mainloop ----------------
// C[M,N] = alpha * A[M,K] @ (TB ? B[N,K]^T : B[K,N])
// Operands are pre-rounded to tf32 (reinterpret loads), except CVTA=true rounds A in-loop.
// OMODE 0: fp32 raw C. OMODE 1: tf32-rounded C. OMODE 2: KV split (col<768 -> K rounded, else V rounded; ld NE).
template <bool TB, int OMODE, bool CVTA>
__global__ __launch_bounds__(256) void mma_gemm(
    const float* __restrict__ A, const float* __restrict__ B,
    float* __restrict__ C, float* __restrict__ C2,
    int M, int N, int K, int lda, int ldb, int ldc, float alpha, int dv,
    long sAhi, long sAlo, long sBhi, long sBlo, long sChi, long sClo) {
    const int BM = 128, BN = 128, BK = 16;
    const int APITCH = BK + 4;
    const int BPITCH_NT = BK + 4;
    const int BPITCH_NN = BN + 8;
    const int BSTG = TB ? BN * BPITCH_NT : BK * BPITCH_NN;
    __shared__ __align__(16) float As[3][BM * APITCH];
    __shared__ __align__(16) float Bs[3][BSTG];

    int z = blockIdx.z;
    A += (long)(z / dv) * sAhi + (long)(z % dv) * sAlo;
    B += (long)(z / dv) * sBhi + (long)(z % dv) * sBlo;
    long coff = (long)(z / dv) * sChi + (long)(z % dv) * sClo;

    int m0 = blockIdx.y * BM, n0 = blockIdx.x * BN;
    int tid = threadIdx.x;
    int warp = tid >> 5, lane = tid & 31;
    int g = lane >> 2, tg = lane & 3;
    int wm = (warp & 3) * 32, wn = (warp >> 2) * 64;

    int ar[2], ac[2], br[2], bc[2];
    #pragma unroll
    for (int rep = 0; rep < 2; rep++) {
        int idx = rep * 256 + tid;
        ar[rep] = idx >> 2; ac[rep] = (idx & 3) * 4;
        if (TB) { br[rep] = idx >> 2; bc[rep] = (idx & 3) * 4; }
        else    { br[rep] = idx >> 5; bc[rep] = (idx & 31) * 4; }
    }

    int niter = K / BK;

    auto prefetch = [&](int st, int buf) {
        int k0 = st * BK;
        #pragma unroll
        for (int rep = 0; rep < 2; rep++) {
            CP_ASYNC16(smem_u32(&As[buf][ar[rep] * APITCH + ac[rep]]),
                       &A[(long)(m0 + ar[rep]) * lda + k0 + ac[rep]]);
            if (TB)
                CP_ASYNC16(smem_u32(&Bs[buf][br[rep] * BPITCH_NT + bc[rep]]),
                           &B[(long)(n0 + br[rep]) * ldb + k0 + bc[rep]]);
            else
                CP_ASYNC16(smem_u32(&Bs[buf][br[rep] * BPITCH_NN + bc[rep]]),
                           &B[(long)(k0 + br[rep]) * ldb + n0 + bc[rep]]);
        }
    };

    prefetch(0, 0); CP_COMMIT();
    prefetch(1, 1); CP_COMMIT();

    float acc[2][8][4] = {};

    for (int it = 0; it < niter; it++) {
        int cur = it % 3;
        CP_WAIT(1);
        __syncthreads();

        if (it + 2 < niter) prefetch(it + 2, (it + 2) % 3);
        CP_COMMIT();

        const float* Asc = As[cur];
        const float* Bsc = Bs[cur];
        #pragma unroll
        for (int kk = 0; kk < BK; kk += 8) {
            uint32_t af[2][4], bf[8][2];
            #pragma unroll
            for (int m = 0; m < 2; m++) {
                int row = wm + m * 16;
                if (CVTA) {
                    af[m][0] = to_tf32_u(Asc[(row + g)     * APITCH + kk + tg]);
                    af[m][1] = to_tf32_u(Asc[(row + g + 8) * APITCH + kk + tg]);
                    af[m][2] = to_tf32_u(Asc[(row + g)     * APITCH + kk + tg + 4]);
                    af[m][3] = to_tf32_u(Asc[(row + g + 8) * APITCH + kk + tg + 4]);
                } else {
                    af[m][0] = __float_as_uint(Asc[(row + g)     * APITCH + kk + tg]);
                    af[m][1] = __float_as_uint(Asc[(row + g + 8) * APITCH + kk + tg]);
                    af[m][2] = __float_as_uint(Asc[(row + g)     * APITCH + kk + tg + 4]);
                    af[m][3] = __float_as_uint(Asc[(row + g + 8) * APITCH + kk + tg + 4]);
                }
            }
            #pragma unroll
            for (int n = 0; n < 8; n++) {
                int col = wn + n * 8 + g;
                if (TB) {
                    bf[n][0] = __float_as_uint(Bsc[col * BPITCH_NT + kk + tg]);
                    bf[n][1] = __float_as_uint(Bsc[col * BPITCH_NT + kk + tg + 4]);
                } else {
                    bf[n][0] = __float_as_uint(Bsc[(kk + tg)     * BPITCH_NN + col]);
                    bf[n][1] = __float_as_uint(Bsc[(kk + tg + 4) * BPITCH_NN + col]);
                }
            }
            #pragma unroll
            for (int m = 0; m < 2; m++)
                #pragma unroll
                for (int n = 0; n < 8; n++)
                    mma_tf32(acc[m][n], af[m], bf[n]);
        }
    }

    // ---- epilogue ----
    #pragma unroll
    for (int m = 0; m < 2; m++) {
        #pragma unroll
        for (int n = 0; n < 8; n++) {
            int row = m0 + wm + m * 16 + g;
            int col = n0 + wn + n * 8 + tg * 2;
            float v00 = alpha * acc[m][n][0], v01 = alpha * acc[m][n][1];
            float v10 = alpha * acc[m][n][2], v11 = alpha * acc[m][n][3];
            if (OMODE == 0) {
                *reinterpret_cast<float2*>(&C[coff + (long)row * ldc + col]) = make_float2(v00, v01);
                *reinterpret_cast<float2*>(&C[coff + (long)(row + 8) * ldc + col]) = make_float2(v10, v11);
            } else if (OMODE == 1) {
                *reinterpret_cast<float2*>(&C[coff + (long)row * ldc + col]) =
                    make_float2(to_tf32_f(v00), to_tf32_f(v01));
                *reinterpret_cast<float2*>(&C[coff + (long)(row + 8) * ldc + col]) =
                    make_float2(to_tf32_f(v10), to_tf32_f(v11));
            } else {
                float2 h0 = make_float2(to_tf32_f(v00), to_tf32_f(v01));
                float2 h1 = make_float2(to_tf32_f(v10), to_tf32_f(v11));
                if (col < NE) {   // K half
                    *reinterpret_cast<float2*>(&C[(long)row * NE + col]) = h0;
                    *reinterpret_cast<float2*>(&C[(long)(row + 8) * NE + col]) = h1;
                } else {          // V half
                    *reinterpret_cast<float2*>(&C2[(long)row * NE + col - NE]) = h0;
                    *reinterpret_cast<float2*>(&C2[(long)(row + 8) * NE + col - NE]) = h1;
                }
            }
        }
    }
}

// ---------------- block reductions ----------------
__device__ __forceinline__ float blockReduceMax(float v, float* red) {
    #pragma unroll
    for (int o = 16; o > 0; o >>= 1) v = fmaxf(v, __shfl_xor_sync(0xFFFFFFFFu, v, o));
    int w = threadIdx.x >> 5, lane = threadIdx.x & 31;
    __syncthreads();
    if (lane == 0) red[w] = v;
    __syncthreads();
    v = (lane < (blockDim.x >> 5)) ? red[lane] : -F32_INF;
    #pragma unroll
    for (int o = 16; o > 0; o >>= 1) v = fmaxf(v, __shfl_xor_sync(0xFFFFFFFFu, v, o));
    return v;
}
__device__ __forceinline__ float blockReduceMin(float v, float* red) {
    #pragma unroll
    for (int o = 16; o > 0; o >>= 1) v = fminf(v, __shfl_xor_sync(0xFFFFFFFFu, v, o));
    int w = threadIdx.x >> 5, lane = threadIdx.x & 31;
    __syncthreads();
    if (lane == 0) red[w] = v;
    __syncthreads();
    v = (lane < (blockDim.x >> 5)) ? red[lane] : F32_INF;
    #pragma unroll
    for (int o = 16; o > 0; o >>= 1) v = fminf(v, __shfl_xor_sync(0xFFFFFFFFu, v, o));
    return v;
}
__device__ __forceinline__ float blockReduceSum(float v, float* red) {
    #pragma unroll
    for (int o = 16; o > 0; o >>= 1) v += __shfl_xor_sync(0xFFFFFFFFu, v, o);
    int w = threadIdx.x >> 5, lane = threadIdx.x & 31;
    __syncthreads();
    if (lane == 0) red[w] = v;
    __syncthreads();
    v = (lane < (blockDim.x >> 5)) ? red[lane] : 0.f;
    #pragma unroll
    for (int o = 16; o > 0; o >>= 1) v += __shfl_xor_sync(0xFFFFFFFFu, v, o);
    return v;
}

// ---------------- softmax + differential + min-shift ----------------
__global__ __launch_bounds__(256) void softmax_diff_kernel(
    const void* __restrict__ qmask, const void* __restrict__ kmask,
    float* __restrict__ out_diff) {
    __shared__ float p1[NL];
    __shared__ float p2[NL];
    __shared__ float red[32];

    int bs = blockIdx.x;
    int b = bs >> 9;
    int s = bs & 511;
    int tid = threadIdx.x;
    int mode = g_mask_mode;

    bool qm = mask_at(qmask, bs, mode);
    const float* s1 = g_S + ((long)(b * 2 + 0) * NS + s) * NL;
    const float* s2 = g_S + ((long)(b * 2 + 1) * NS + s) * NL;
    long kmbase = (long)b * NL;

    float m1 = -F32_INF, m2 = -F32_INF;
    for (int l = tid; l < NL; l += 256) {
        bool mk = qm && mask_at(kmask, kmbase + l, mode);
        float v1 = mk ? s1[l] : -1e20f;
        float v2 = mk ? s2[l] : -1e20f;
        p1[l] = v1; p2[l] = v2;
        m1 = fmaxf(m1, v1); m2 = fmaxf(m2, v2);
    }
    m1 = blockReduceMax(m1, red);
    m2 = blockReduceMax(m2, red);

    float sum1 = 0.f, sum2 = 0.f;
    for (int l = tid; l < NL; l += 256) {
        float e1 = expf(p1[l] - m1);
        float e2 = expf(p2[l] - m2);
        p1[l] = e1; p2[l] = e2;
        sum1 += e1; sum2 += e2;
    }
    sum1 = blockReduceSum(sum1, red);
    sum2 = blockReduceSum(sum2, red);
    float inv1 = 1.f / (sum1 + 1e-8f);
    float inv2 = 1.f / (sum2 + 1e-8f);
    float lam = g_lambda;

    float mn = F32_INF;
    for (int l = tid; l < NL; l += 256) {
        float d = p1[l] * inv1 - lam * (p2[l] * inv2);
        p1[l] = d;
        mn = fminf(mn, d);
    }
    mn = blockReduceMin(mn, red);

    float* od = out_diff + (long)bs * NL;
    for (int l = tid; l < NL; l += 256) {
        bool mk = qm && mask_at(kmask, kmbase + l, mode);
        od[l] = mk ? (p1[l] - mn + 1e-20f) : 0.f;
    }
}

// ---------------- split-K reduce + RMS norm (fused), writes tf32-rounded X ----------------
__global__ __launch_bounds__(256) void rmsnorm_kernel(const float* __restrict__ ln) {
    __shared__ float red[32];
    __shared__ float row_buf[NE];
    int row = blockIdx.x;
    int tid = threadIdx.x;
    const long rbase = (long)row * NE;
    const long pstride = (long)NB * NS * NE;
    float ss = 0.f;
    for (int e = tid; e < NE; e += 256) {
        float v = g_P[rbase + e] + g_P[pstride + rbase + e]
                + g_P[2 * pstride + rbase + e] + g_P[3 * pstride + rbase + e];
        row_buf[e] = v;
        ss += v * v;
    }
    ss = blockReduceSum(ss, red);
    float scale = rsqrtf(ss / (float)NE + 1e-5f) * (1.0f - LAMBDA_INIT);
    float* x = g_X + rbase;
    for (int e = tid; e < NE; e += 256) x[e] = to_tf32_f(row_buf[e] * scale * ln[e]);
}

// ---------------- launch ----------------
extern "C" void kernel_launch(void* const* d_in, const int* in_sizes, int n_in,
                              void* d_out, int out_size) {
    const float* query = (const float*)d_in[0];   // (8,512,768)
    const float* key   = (const float*)d_in[1];   // (8,64,64,32)
    const void*  qmask = d_in[2];                 // (8,512)
    const void*  kmask = d_in[3];                 // (8,64,64)
    const float* Wq   = (const float*)d_in[4];
    const float* Wkv  = (const float*)d_in[5];
    const float* Wout = (const float*)d_in[6];
    const float* lq1  = (const float*)d_in[7];
    const float* lk1  = (const float*)d_in[8];
    const float* lq2  = (const float*)d_in[9];
    const float* lk2  = (const float*)d_in[10];
    const float* ln   = (const float*)d_in[11];

    float* outp = (float*)d_out;                       // (8,512,768)
    float* diffp = outp + (long)NB * NS * NE;          // (8,512,64,64)

    float *pQI, *pKI, *pW1, *pW2, *pW3, *pQ, *pK, *pV, *pS, *pP, *pX;
    cudaGetSymbolAddress((void**)&pQI, g_QI);
    cudaGetSymbolAddress((void**)&pKI, g_KI);
    cudaGetSymbolAddress((void**)&pW1, g_W1);
    cudaGetSymbolAddress((void**)&pW2, g_W2);
    cudaGetSymbolAddress((void**)&pW3, g_W3);
    cudaGetSymbolAddress((void**)&pQ,  g_Q);
    cudaGetSymbolAddress((void**)&pK,  g_K);
    cudaGetSymbolAddress((void**)&pV,  g_V);
    cudaGetSymbolAddress((void**)&pS,  g_S);
    cudaGetSymbolAddress((void**)&pP,  g_P);
    cudaGetSymbolAddress((void**)&pX,  g_X);

    detect_mask_kernel<<<1, 256>>>((const unsigned char*)kmask);
    lambda_kernel<<<1, 384>>>(lq1, lk1, lq2, lk2);

    // pre-round inputs/weights to tf32 (grid-stride float4)
    round_tf32_kernel<<<(NB * NS * NE / 4 + 255) / 256, 256>>>(query, pQI, NB * NS * NE / 4);
    round_tf32_kernel<<<(NB * NL * NGE / 4 + 255) / 256, 256>>>(key, pKI, NB * NL * NGE / 4);
    round_tf32_kernel<<<(NE * NE / 4 + 255) / 256, 256>>>(Wq, pW1, NE * NE / 4);
    round_tf32_kernel<<<(NGE * 2 * NE / 4 + 255) / 256, 256>>>(Wkv, pW2, NGE * 2 * NE / 4);
    round_tf32_kernel<<<(NE * NE / 4 + 255) / 256, 256>>>(Wout, pW3, NE * NE / 4);

    // Q = queryR @ WqR -> tf32-rounded : M=4096, N=768, K=768
    mma_gemm<false, 1, false><<<dim3(NE / 128, (NB * NS) / 128, 1), 256>>>(
        pQI, pW1, pQ, nullptr, NB * NS, NE, NE, NE, NE, NE, 1.0f,
        1, 0, 0, 0, 0, 0, 0);

    // KV = keyR @ WkvR -> K | V (both tf32-rounded, ld 768) : M=32768, N=1536, K=32
    mma_gemm<false, 2, false><<<dim3((2 * NE) / 128, (NB * NL) / 128, 1), 256>>>(
        pKI, pW2, pK, pV, NB * NL, 2 * NE, NGE, NGE, 2 * NE, NE, 1.0f,
        1, 0, 0, 0, 0, 0, 0);

    // scores = SCALING * Qh @ Kh^T : M=512, N=4096, K=384, 16 batches (b,h)
    mma_gemm<true, 0, false><<<dim3(NL / 128, NS / 128, NB * 2), 256>>>(
        pQ, pK, pS, nullptr, NS, NL, NHD, NE, NE, NL, SCALING,
        2,
        (long)NS * NE, (long)NHD,
        (long)NL * NE, (long)NHD,
        (long)2 * NS * NL, (long)NS * NL);

    // softmax + diff + min-shift -> d_out diff region
    softmax_diff_kernel<<<NB * NS, 256>>>(qmask, kmask, diffp);

    // attn_out partials: A=diff (exact fp32, cvt in-loop), B=V (pre-rounded)
    mma_gemm<false, 0, true><<<dim3(NE / 128, NS / 128, NB * KSPLIT), 256>>>(
        diffp, pV, pP, nullptr, NS, NE, NL / KSPLIT, NL, NE, NE, 1.0f,
        KSPLIT,
        (long)NS * NL, (long)(NL / KSPLIT),
        (long)NL * NE, (long)(NL / KSPLIT) * NE,
        (long)NS * NE, (long)NB * NS * NE);

    // split-K reduce + RMS norm (writes tf32-rounded X)
    rmsnorm_kernel<<<NB * NS, 256>>>(ln);

    // out = XR @ WoutR : M=4096, N=768, K=768
    mma_gemm<false, 0, false><<<dim3(NE / 128, (NB * NS) / 128, 1), 256>>>(
        pX, pW3, outp, nullptr, NB * NS, NE, NE, NE, NE, NE, 1.0f,
        1, 0, 0, 0, 0, 0, 0);
}